// round 7
// baseline (speedup 1.0000x reference)
#include <cuda_runtime.h>
#include <cstdint>

// Embedding gather, async two-stage pipeline (sm_103a).
// x: [32768] int32; emb: [50257, 512] f32; out: [32768, 512] f32.
// even ids -> id 0 (reference: jnp.where(x % 2 == 0, 0, x)).
//
// Stage 1: cp.async.ca.shared.global (LDGSTS, 16B) gathers 16 rows into a
//          32KB smem tile. No register writeback -> warps never stall on
//          load latency; one wait_group at the end.
// Stage 2: the 16 output rows are CONTIGUOUS in gmem, so one elected
//          cp.async.bulk ships the whole 32KB tile smem->gmem, bypassing
//          L1tex and the register file on the store side entirely.

static constexpr int ROW_BYTES      = 2048;   // 512 f32
static constexpr int ROWS_PER_BLOCK = 16;
static constexpr int THREADS        = 256;
static constexpr int TILE_BYTES     = ROWS_PER_BLOCK * ROW_BYTES;  // 32768
static constexpr int COPIES         = TILE_BYTES / (THREADS * 16); // 8

__device__ __forceinline__ uint32_t smem_u32(const void* p) {
    return (uint32_t)__cvta_generic_to_shared(p);
}

__global__ __launch_bounds__(THREADS)
void embed_async_kernel(const int* __restrict__ x,
                        const char* __restrict__ emb,
                        char* __restrict__ out,
                        int n_rows) {
    __shared__ alignas(128) char stage[TILE_BYTES];
    __shared__ int toks[ROWS_PER_BLOCK];

    const int base = blockIdx.x * ROWS_PER_BLOCK;
    const int tid  = threadIdx.x;

    if (tid < ROWS_PER_BLOCK) {
        int r = base + tid;
        int tok = (r < n_rows) ? x[r] : 0;
        toks[tid] = (tok & 1) ? tok : 0;   // even ids -> row 0
    }
    __syncthreads();

    // Flat float4 index space over the tile: i = c*256 + tid, i in [0, 2048).
    // row = i>>7, col = i&127. smem dst offset = i*16 (linear tile layout,
    // which is exactly the gmem layout of the 16 consecutive output rows).
    const uint32_t s0 = smem_u32(stage);
#pragma unroll
    for (int c = 0; c < COPIES; c++) {
        int i   = c * THREADS + tid;
        int row = i >> 7;
        int col = i & 127;
        const char* src = emb + (size_t)toks[row] * ROW_BYTES + col * 16;
        uint32_t dst = s0 + (uint32_t)i * 16;
        asm volatile("cp.async.ca.shared.global [%0], [%1], 16;"
                     :: "r"(dst), "l"(src) : "memory");
    }
    asm volatile("cp.async.commit_group;" ::: "memory");
    asm volatile("cp.async.wait_group 0;" ::: "memory");
    __syncthreads();

    // Single bulk store: smem tile -> 32KB contiguous output block.
    if (tid == 0) {
        // Generic-proxy smem writes (cp.async fills) -> async-proxy read.
        asm volatile("fence.proxy.async.shared::cta;" ::: "memory");
        char* dst = out + (size_t)base * ROW_BYTES;
        asm volatile(
            "cp.async.bulk.global.shared::cta.bulk_group [%0], [%1], %2;"
            :: "l"(dst), "r"(s0), "n"(TILE_BYTES) : "memory");
        asm volatile("cp.async.bulk.commit_group;" ::: "memory");
        // Full completion before CTA exit (smem slot reuse + kernel-boundary
        // visibility).
        asm volatile("cp.async.bulk.wait_group 0;" ::: "memory");
    }
}

extern "C" void kernel_launch(void* const* d_in, const int* in_sizes, int n_in,
                              void* d_out, int out_size) {
    const int* x    = (const int*)d_in[0];
    const char* emb = (const char*)d_in[1];
    char* out       = (char*)d_out;

    int n_rows   = in_sizes[0];                                       // 32768
    int n_blocks = (n_rows + ROWS_PER_BLOCK - 1) / ROWS_PER_BLOCK;    // 2048

    embed_async_kernel<<<n_blocks, THREADS>>>(x, emb, out, n_rows);
}

// round 8
// speedup vs baseline: 1.3607x; 1.3607x over previous
#include <cuda_runtime.h>
#include <cstdint>

// Embedding gather with even-token-id remap to 0.
// x: [32768] int32; emb: [50257, 512] f32; out: [32768, 512] f32.
// even ids -> id 0 (reference: jnp.where(x % 2 == 0, 0, x)).
//
// ~half of all tokens are even -> row 0. Each chunk's row is warp-uniform
// (threads 0..127 = row 2c, threads 128..255 = row 2c+1), so we register-
// cache row 0 (one LDG per thread) and predicate away the LDG for even
// rows entirely: ~half of all load wavefronts through L1tex disappear.

static constexpr int VEC_PER_ROW    = 128;  // float4 per row
static constexpr int ROWS_PER_BLOCK = 16;
static constexpr int THREADS        = 256;
static constexpr int CHUNKS         = 8;

__global__ __launch_bounds__(THREADS)
void embed_gather_kernel(const int* __restrict__ x,
                         const float4* __restrict__ emb,
                         float4* __restrict__ out,
                         int n_rows) {
    __shared__ int toks[ROWS_PER_BLOCK];

    const int base = blockIdx.x * ROWS_PER_BLOCK;
    const int tid  = threadIdx.x;

    if (tid < ROWS_PER_BLOCK) {
        int r = base + tid;
        int tok = (r < n_rows) ? x[r] : 0;
        toks[tid] = (tok & 1) ? tok : 0;   // even ids -> row 0
    }

    const int rhi = tid >> 7;   // 0 or 1: which row of the chunk pair
    const int col = tid & 127;  // float4 column within the row

    // Row 0 column value, loaded once (L1/L2-hot across the whole grid).
    const float4 r0 = __ldg(emb + col);

    __syncthreads();

    int t0 = toks[ 0 + rhi];
    int t1 = toks[ 2 + rhi];
    int t2 = toks[ 4 + rhi];
    int t3 = toks[ 6 + rhi];
    int t4 = toks[ 8 + rhi];
    int t5 = toks[10 + rhi];
    int t6 = toks[12 + rhi];
    int t7 = toks[14 + rhi];

    // Warp-uniform predicated gathers: even rows (tok==0) use the cached
    // register instead of issuing an LDG.
    float4 v0 = t0 ? __ldg(emb + (size_t)t0 * VEC_PER_ROW + col) : r0;
    float4 v1 = t1 ? __ldg(emb + (size_t)t1 * VEC_PER_ROW + col) : r0;
    float4 v2 = t2 ? __ldg(emb + (size_t)t2 * VEC_PER_ROW + col) : r0;
    float4 v3 = t3 ? __ldg(emb + (size_t)t3 * VEC_PER_ROW + col) : r0;
    float4 v4 = t4 ? __ldg(emb + (size_t)t4 * VEC_PER_ROW + col) : r0;
    float4 v5 = t5 ? __ldg(emb + (size_t)t5 * VEC_PER_ROW + col) : r0;
    float4 v6 = t6 ? __ldg(emb + (size_t)t6 * VEC_PER_ROW + col) : r0;
    float4 v7 = t7 ? __ldg(emb + (size_t)t7 * VEC_PER_ROW + col) : r0;

    // Store: chunk c writes flat float4 index c*256 + tid of the CTA tile.
    float4* dst = out + (size_t)base * VEC_PER_ROW + tid;
    dst[0 * THREADS] = v0;
    dst[1 * THREADS] = v1;
    dst[2 * THREADS] = v2;
    dst[3 * THREADS] = v3;
    dst[4 * THREADS] = v4;
    dst[5 * THREADS] = v5;
    dst[6 * THREADS] = v6;
    dst[7 * THREADS] = v7;
}

extern "C" void kernel_launch(void* const* d_in, const int* in_sizes, int n_in,
                              void* d_out, int out_size) {
    const int* x      = (const int*)d_in[0];
    const float4* emb = (const float4*)d_in[1];
    float4* out       = (float4*)d_out;

    int n_rows   = in_sizes[0];  // 32768
    int n_blocks = (n_rows + ROWS_PER_BLOCK - 1) / ROWS_PER_BLOCK;  // 2048

    embed_gather_kernel<<<n_blocks, THREADS>>>(x, emb, out, n_rows);
}